// round 8
// baseline (speedup 1.0000x reference)
#include <cuda_runtime.h>
#include <cuda_pipeline.h>
#include <cstdint>
#include <cstddef>

// Problem constants
#define BATCH 8
#define TSEQ  1024
#define DDIM  384
#define DLANG 768
#define HID   512

#define NB   128      // one wave (<= 148 SMs), all blocks co-resident
#define NTHR 256
#define KSPLIT 4

// Scratch + barrier state (allocation-free rule: __device__ globals)
// Partial buffers: part[ks][b][j]  (ks-split GEMV partials; consumer sums)
__device__ float g_partA[KSPLIT * BATCH * HID];   // 16K floats
__device__ float g_partB[KSPLIT * BATCH * HID];
__device__ unsigned g_barrier[8];   // zeroed each launch via captured cudaMemsetAsync

// Dynamic smem layout:
//   float4 tile[6144]   : 98304 B (state tile: 64 rows x 96 float4)
//   float4 wbuf[4096]   : 65536 B (prefetched weight slice: 128 k x 32 f4)
//   float  sin[192]     :   768 B (input k-slice)
//   float4 spart[256]   :  4096 B (8 warps x 32 col-groups)
//   float4 fsh[96]      :  1536 B (f row)
//   uint64 mbar         :    16 B
#define TILE_F4 6144
#define WBUF_F4 4096
#define SMEM_BYTES (TILE_F4 * 16 + WBUF_F4 * 16 + 192 * 4 + 256 * 16 + 96 * 16 + 16)

extern __shared__ float4 smem_dyn[];

__device__ __forceinline__ uint32_t smem_u32(const void* p) {
    return (uint32_t)__cvta_generic_to_shared(p);
}

// ---------------------------------------------------------------------------
// Grid barrier (all NB blocks): single-lane RED + L2 spin.
// ---------------------------------------------------------------------------
__device__ __forceinline__ void grid_barrier(int phase) {
    __syncthreads();
    if (threadIdx.x == 0) {
        __threadfence();
        atomicAdd(&g_barrier[phase], 1u);   // result unused -> RED
        volatile unsigned* p = &g_barrier[phase];
        while (*p < NB) { __nanosleep(16); }
        __threadfence();
    }
    __syncthreads();
}

// ---------------------------------------------------------------------------
// Weight prefetch into smem via cp.async (stages with K4 == 128 only).
// Block (ks, idx): slice = W[ks*128 .. +128][jt*128 .. +128 cols].
// 4096 float4 over 256 threads = 16 each, coalesced.
// ---------------------------------------------------------------------------
template <int NC4, int JT>
__device__ __forceinline__ void prefetch_w(const float* __restrict__ W,
                                           float4* wbuf, int active_tasks) {
    const int ks  = blockIdx.x >> 5;
    const int idx = blockIdx.x & 31;
    if (idx < active_tasks) {
        const int jt = idx % JT;
        const float4* W4 = (const float4*)W;
#pragma unroll
        for (int i = 0; i < 16; ++i) {
            const int l = threadIdx.x + i * 256;   // 0..4095
            const int r = l >> 5, c = l & 31;
            __pipeline_memcpy_async(
                &wbuf[l],
                &W4[(size_t)(ks * 128 + r) * NC4 + jt * 32 + c], 16);
        }
        __pipeline_commit();
    }
}

// ---------------------------------------------------------------------------
// Stage 0 (direct-LDG): K=768, K4=192, KW=24, N=512, JT=4, input is dense.
// ---------------------------------------------------------------------------
__device__ __forceinline__ void stage0(const float* __restrict__ in,
                                       const float* __restrict__ W,
                                       const float* __restrict__ bias,
                                       float* __restrict__ out_part,
                                       float* sin, float4* spart) {
    constexpr int K = DLANG, N = HID, JT = 4, K4 = K / KSPLIT, KW = K4 / 8;
    const int ks  = blockIdx.x >> 5;
    const int idx = blockIdx.x & 31;
    const int b  = idx / JT;
    const int jt = idx % JT;

    if (threadIdx.x < K4)
        sin[threadIdx.x] = in[(size_t)b * K + ks * K4 + threadIdx.x];
    __syncthreads();

    const int w  = threadIdx.x >> 5;
    const int j4 = threadIdx.x & 31;
    constexpr int NC4 = N / 4;
    const float4* Wp = (const float4*)W
                     + (size_t)(ks * K4 + w * KW) * NC4 + jt * 32 + j4;
    const float* sp = sin + w * KW;
    float4 acc = {0.f, 0.f, 0.f, 0.f};
#pragma unroll
    for (int i = 0; i < KW; ++i) {
        const float s = sp[i];
        const float4 wv = Wp[(size_t)i * NC4];
        acc.x += s * wv.x; acc.y += s * wv.y;
        acc.z += s * wv.z; acc.w += s * wv.w;
    }
    spart[w * 32 + j4] = acc;
    __syncthreads();

    if (threadIdx.x < 32) {
        float4 s = spart[threadIdx.x];
#pragma unroll
        for (int k = 1; k < 8; ++k) {
            const float4 v = spart[k * 32 + threadIdx.x];
            s.x += v.x; s.y += v.y; s.z += v.z; s.w += v.w;
        }
        if (ks == 0) {
            const float4 bb = ((const float4*)bias)[jt * 32 + threadIdx.x];
            s.x += bb.x; s.y += bb.y; s.z += bb.z; s.w += bb.w;
        }
        ((float4*)(out_part + (size_t)(ks * BATCH + b) * N))
            [jt * 32 + threadIdx.x] = s;
    }
}

// ---------------------------------------------------------------------------
// Prefetched stage (K = 512 -> K4 = 128, KW = 16). Input = 4 partials summed
// in fixed order (deterministic). Weights already streaming into wbuf.
// ---------------------------------------------------------------------------
template <int N, int JT>
__device__ __forceinline__ void stage_smem(const float* __restrict__ in,
                                           const float* __restrict__ bias,
                                           float* __restrict__ out_part,
                                           const float4* wbuf,
                                           float* sin, float4* spart) {
    constexpr int K = HID, K4 = K / KSPLIT, KW = K4 / 8;
    const int ks  = blockIdx.x >> 5;
    const int idx = blockIdx.x & 31;
    const bool active = idx < 8 * JT;
    const int b  = idx / JT;
    const int jt = idx % JT;

    if (active && threadIdx.x < K4) {
        const size_t o = (size_t)b * K + ks * K4 + threadIdx.x;
        float s = in[o];
        s += in[(size_t)(1 * BATCH) * K + o];
        s += in[(size_t)(2 * BATCH) * K + o];
        s += in[(size_t)(3 * BATCH) * K + o];
        sin[threadIdx.x] = s;
    }
    __pipeline_wait_prior(0);          // weight slice resident in wbuf
    __syncthreads();

    if (active) {
        const int w  = threadIdx.x >> 5;
        const int j4 = threadIdx.x & 31;
        const float4* wp = wbuf + (w * KW) * 32 + j4;
        const float* sp = sin + w * KW;
        float4 acc = {0.f, 0.f, 0.f, 0.f};
#pragma unroll
        for (int i = 0; i < KW; ++i) {
            const float s = sp[i];
            const float4 wv = wp[i * 32];
            acc.x += s * wv.x; acc.y += s * wv.y;
            acc.z += s * wv.z; acc.w += s * wv.w;
        }
        spart[w * 32 + j4] = acc;
    }
    __syncthreads();                   // wbuf free after this point

    if (active && threadIdx.x < 32) {
        float4 s = spart[threadIdx.x];
#pragma unroll
        for (int k = 1; k < 8; ++k) {
            const float4 v = spart[k * 32 + threadIdx.x];
            s.x += v.x; s.y += v.y; s.z += v.z; s.w += v.w;
        }
        if (ks == 0) {
            const float4 bb = ((const float4*)bias)[jt * 32 + threadIdx.x];
            s.x += bb.x; s.y += bb.y; s.z += bb.z; s.w += bb.w;
        }
        ((float4*)(out_part + (size_t)(ks * BATCH + b) * N))
            [jt * 32 + threadIdx.x] = s;
    }
}

// ---------------------------------------------------------------------------
// Fused kernel.
//
// Math note: language is broadcast along T, so k/v are identical for all key
// positions; softmax over a constant row is exactly uniform 1/T and ctx == v.
// The Q path and the T x T attention cancel analytically:
//   f[b] = (((language[b] Wv + bv) Wv2 + bv2) Wo + bo) Wout + bout
//   out[b,t,:] = state[b,t,:] + f[b,:]
//
// Overlap: one cp.async.bulk per block streams the 96KB state tile on the TMA
// pipe during the whole chain; each chain stage's weight slice is cp.async-
// prefetched into smem during the PREVIOUS stage + barrier spin, so the
// post-barrier critical path contains no cold weight loads.
// ---------------------------------------------------------------------------
__global__ void __launch_bounds__(NTHR, 1)
fused_cma_kernel(const float* __restrict__ state,
                 const float* __restrict__ language,
                 const float* __restrict__ Wv,  const float* __restrict__ bv,
                 const float* __restrict__ Wv2, const float* __restrict__ bv2,
                 const float* __restrict__ Wo,  const float* __restrict__ bo,
                 const float* __restrict__ Wout,const float* __restrict__ bout,
                 float* __restrict__ out) {
    float4*   tile  = smem_dyn;                              // 6144 float4
    float4*   wbuf  = smem_dyn + TILE_F4;                    // 4096 float4
    float*    sin   = (float*)(wbuf + WBUF_F4);              // 192 floats
    float4*   spart = (float4*)(sin + 192);                  // 256 float4
    float4*   fsh   = spart + 256;                           // 96 float4
    uint64_t* mbar  = (uint64_t*)(fsh + 96);

    // ---- Issue state-tile bulk copy first (TMA pipe; overlaps the chain) ----
    const int bres = blockIdx.x >> 4;                        // batch
    const int t0   = (blockIdx.x & 15) * 64;                 // row start
    const size_t base = ((size_t)bres * TSEQ + t0) * DDIM;

    const uint32_t mbar_s = smem_u32(mbar);
    const uint32_t tile_s = smem_u32(tile);
    if (threadIdx.x == 0) {
        asm volatile("mbarrier.init.shared.b64 [%0], 1;" :: "r"(mbar_s) : "memory");
        asm volatile("fence.proxy.async.shared::cta;" ::: "memory");
        asm volatile("mbarrier.arrive.expect_tx.shared.b64 _, [%0], %1;"
                     :: "r"(mbar_s), "r"((unsigned)(TILE_F4 * 16)) : "memory");
        asm volatile(
            "cp.async.bulk.shared::cta.global.mbarrier::complete_tx::bytes "
            "[%0], [%1], %2, [%3];"
            :: "r"(tile_s), "l"(state + base), "r"((unsigned)(TILE_F4 * 16)),
               "r"(mbar_s) : "memory");
    }

    // ---- GEMV chain: 4 stages, all blocks, K-split partials ----
    prefetch_w<HID / 4, 4>(Wv2, wbuf, 32);       // stage1 weights, hidden behind stage0
    stage0(language, Wv, bv, g_partA, sin, spart);
    grid_barrier(0);

    stage_smem<HID, 4>(g_partA, bv2, g_partB, wbuf, sin, spart);
    prefetch_w<HID / 4, 4>(Wo, wbuf, 32);        // stage2 weights, hidden behind barrier
    grid_barrier(1);

    stage_smem<HID, 4>(g_partB, bo, g_partA, wbuf, sin, spart);
    prefetch_w<DDIM / 4, 3>(Wout, wbuf, 24);     // stage3 weights
    grid_barrier(2);

    stage_smem<DDIM, 3>(g_partA, bout, g_partB, wbuf, sin, spart);
    grid_barrier(3);

    // ---- Assemble f row for this block's batch (deterministic sum) ----
    if (threadIdx.x < DDIM / 4) {
        const float4* p0 = (const float4*)(g_partB + (size_t)(0 * BATCH + bres) * DDIM);
        const float4* p1 = (const float4*)(g_partB + (size_t)(1 * BATCH + bres) * DDIM);
        const float4* p2 = (const float4*)(g_partB + (size_t)(2 * BATCH + bres) * DDIM);
        const float4* p3 = (const float4*)(g_partB + (size_t)(3 * BATCH + bres) * DDIM);
        float4 a = p0[threadIdx.x], b = p1[threadIdx.x];
        float4 c = p2[threadIdx.x], d = p3[threadIdx.x];
        a.x += b.x; a.y += b.y; a.z += b.z; a.w += b.w;
        c.x += d.x; c.y += d.y; c.z += d.z; c.w += d.w;
        a.x += c.x; a.y += c.y; a.z += c.z; a.w += c.w;
        fsh[threadIdx.x] = a;
    }
    __syncthreads();

    // Register-resident f values: the dq sequence (stride 64 mod 96) has
    // period 3, so each thread touches only 3 distinct f float4s.
    const int dq0 = threadIdx.x % (DDIM / 4);
    const int dq1 = (dq0 + 64) % (DDIM / 4);
    const int dq2 = (dq0 + 32) % (DDIM / 4);
    const float4 f0 = fsh[dq0], f1 = fsh[dq1], f2 = fsh[dq2];

    // ---- Wait for the state tile (mbarrier parity 0, acquire) ----
    {
        uint32_t done;
        asm volatile(
            "{\n\t.reg .pred p;\n\t"
            "mbarrier.try_wait.parity.acquire.cta.shared::cta.b64 p, [%1], 0;\n\t"
            "selp.b32 %0, 1, 0, p;\n\t}"
            : "=r"(done) : "r"(mbar_s) : "memory");
        if (!done) {
            asm volatile(
                "{\n\t.reg .pred P1;\n\t"
                "WL_%=:\n\t"
                "mbarrier.try_wait.parity.acquire.cta.shared::cta.b64 P1, [%0], 0, 0x989680;\n\t"
                "@P1 bra.uni WD_%=;\n\t"
                "bra.uni WL_%=;\n\t"
                "WD_%=:\n\t}"
                :: "r"(mbar_s) : "memory");
        }
    }

    // ---- Residual add + store: 6144 float4 per block, 24 per thread ----
    float4* op = (float4*)(out + base);
#pragma unroll
    for (int it = 0; it < 24; ++it) {
        const int p = threadIdx.x + it * NTHR;
        float4 s = tile[p];
        const float4 fv = (it % 3 == 0) ? f0 : ((it % 3 == 1) ? f1 : f2);
        s.x += fv.x; s.y += fv.y; s.z += fv.z; s.w += fv.w;
        op[p] = s;
    }
}

// ---------------------------------------------------------------------------
// Inputs (metadata order):
//  0 state [B,T,D]   1 language [B,DL]
//  2 Wq 3 bq 4 Wk 5 bk 6 Wv 7 bv
//  8 Wq2 9 bq2 10 Wk2 11 bk2 12 Wv2 13 bv2
// 14 Wo 15 bo 16 Wout 17 bout
// Output: float32 [B,T,D]
// ---------------------------------------------------------------------------
extern "C" void kernel_launch(void* const* d_in, const int* in_sizes, int n_in,
                              void* d_out, int out_size) {
    (void)in_sizes; (void)n_in; (void)out_size;

    const float* state    = (const float*)d_in[0];
    const float* language = (const float*)d_in[1];
    const float* Wv   = (const float*)d_in[6];
    const float* bv   = (const float*)d_in[7];
    const float* Wv2  = (const float*)d_in[12];
    const float* bv2  = (const float*)d_in[13];
    const float* Wo   = (const float*)d_in[14];
    const float* bo   = (const float*)d_in[15];
    const float* Wout = (const float*)d_in[16];
    const float* bout = (const float*)d_in[17];
    float* out = (float*)d_out;

    cudaFuncSetAttribute(fused_cma_kernel,
                         cudaFuncAttributeMaxDynamicSharedMemorySize,
                         SMEM_BYTES);

    unsigned* barp = nullptr;
    cudaGetSymbolAddress((void**)&barp, g_barrier);

    // Reset barrier counters each launch (async memset is graph-capturable).
    cudaMemsetAsync(barp, 0, sizeof(g_barrier));

    fused_cma_kernel<<<NB, NTHR, SMEM_BYTES>>>(state, language,
                                               Wv, bv, Wv2, bv2, Wo, bo,
                                               Wout, bout, out);
}

// round 9
// speedup vs baseline: 1.1319x; 1.1319x over previous
#include <cuda_runtime.h>
#include <cstdint>
#include <cstddef>

// Problem constants
#define BATCH 8
#define TSEQ  1024
#define DDIM  384
#define DLANG 768
#define HID   512

#define NB   128      // one wave (<= 148 SMs), all blocks co-resident
#define NTHR 512      // 16 warps/SM: latency hiding for every phase
#define KSPLIT 4

// Scratch + barrier state (allocation-free rule: __device__ globals)
// Partial buffers: part[ks][b][j]  (ks-split GEMV partials; consumer sums)
__device__ float g_partA[KSPLIT * BATCH * HID];
__device__ float g_partB[KSPLIT * BATCH * HID];
__device__ unsigned g_barrier[8];   // monotonic ticket counters; NEVER reset

// Dynamic smem layout:
//   float4 tile[6144]   : 98304 B (state tile: 64 rows x 96 float4)
//   float  sin[192]     :   768 B (input k-slice)
//   float4 spart[512]   :  8192 B (16 warps x 32 col-groups)
//   float4 fsh[96]      :  1536 B (f row)
//   uint64 mbar         :    16 B
#define TILE_F4 6144
#define SMEM_BYTES (TILE_F4 * 16 + 192 * 4 + 512 * 16 + 96 * 16 + 16)

extern __shared__ float4 smem_dyn[];

__device__ __forceinline__ uint32_t smem_u32(const void* p) {
    return (uint32_t)__cvta_generic_to_shared(p);
}

// ---------------------------------------------------------------------------
// Monotonic ticket grid barrier: no reset needed across graph replays.
// Replays are stream-serialized, so at each replay the counter starts at a
// clean multiple of NB; target = next multiple above my ticket.
// ---------------------------------------------------------------------------
__device__ __forceinline__ void grid_barrier(int phase) {
    __syncthreads();
    if (threadIdx.x == 0) {
        __threadfence();
        const unsigned old = atomicAdd(&g_barrier[phase], 1u);
        const unsigned target = old - (old % NB) + NB;
        volatile unsigned* p = &g_barrier[phase];
        while ((int)(*p - target) < 0) { __nanosleep(16); }
        __threadfence();
    }
    __syncthreads();
}

// ---------------------------------------------------------------------------
// One K-split GEMV stage across all 128 blocks (direct LDG weights).
//   block -> (ks, idx): ks = blockIdx.x>>5, idx = blockIdx.x&31
//   active if idx < 8*JT;  b = idx/JT; jt = idx%JT (tile of 128 columns)
//   partial[ks][b][j] = sum_{i in ks-slice} in[b,i]*W[i,j]  (+bias if ks==0)
// FIRST: input is dense [B][K]; else input = partials [KSPLIT][B][K] summed
// in fixed order (deterministic).
// 16 warps: warp = k-subslice (KW = K/KSPLIT/16), thread = float4 col group.
// ---------------------------------------------------------------------------
template <int K, int N, int JT, bool FIRST>
__device__ __forceinline__ void chain_stage(const float* __restrict__ in,
                                            const float* __restrict__ W,
                                            const float* __restrict__ bias,
                                            float* __restrict__ out_part,
                                            float* sin, float4* spart) {
    constexpr int K4 = K / KSPLIT;      // 192 or 128
    constexpr int KW = K4 / 16;         // 12 or 8
    const int ks  = blockIdx.x >> 5;
    const int idx = blockIdx.x & 31;
    const bool active = idx < 8 * JT;
    const int b  = idx / JT;
    const int jt = idx % JT;

    if (active && threadIdx.x < K4) {
        if (FIRST) {
            sin[threadIdx.x] = in[(size_t)b * K + ks * K4 + threadIdx.x];
        } else {
            const size_t o = (size_t)b * K + ks * K4 + threadIdx.x;
            float s = in[o];
            s += in[(size_t)(1 * BATCH) * K + o];
            s += in[(size_t)(2 * BATCH) * K + o];
            s += in[(size_t)(3 * BATCH) * K + o];
            sin[threadIdx.x] = s;
        }
    }
    __syncthreads();

    if (active) {
        const int w  = threadIdx.x >> 5;       // 0..15
        const int j4 = threadIdx.x & 31;
        constexpr int NC4 = N / 4;
        const float4* Wp = (const float4*)W
                         + (size_t)(ks * K4 + w * KW) * NC4 + jt * 32 + j4;
        const float* sp = sin + w * KW;
        float4 acc = {0.f, 0.f, 0.f, 0.f};
#pragma unroll
        for (int i = 0; i < KW; ++i) {
            const float s = sp[i];
            const float4 wv = Wp[(size_t)i * NC4];
            acc.x += s * wv.x; acc.y += s * wv.y;
            acc.z += s * wv.z; acc.w += s * wv.w;
        }
        spart[w * 32 + j4] = acc;
    }
    __syncthreads();

    if (active && threadIdx.x < 32) {
        float4 s = spart[threadIdx.x];
#pragma unroll
        for (int k = 1; k < 16; ++k) {
            const float4 v = spart[k * 32 + threadIdx.x];
            s.x += v.x; s.y += v.y; s.z += v.z; s.w += v.w;
        }
        if (ks == 0) {
            const float4 bb = ((const float4*)bias)[jt * 32 + threadIdx.x];
            s.x += bb.x; s.y += bb.y; s.z += bb.z; s.w += bb.w;
        }
        ((float4*)(out_part + (size_t)(ks * BATCH + b) * N))
            [jt * 32 + threadIdx.x] = s;
    }
    // sin/spart reuse by the next stage is protected by grid_barrier's syncs.
}

// ---------------------------------------------------------------------------
// Fused kernel.
//
// Math note: language is broadcast along T, so k/v are identical for all key
// positions; softmax over a constant row is exactly uniform 1/T and ctx == v.
// The Q path and the T x T attention cancel analytically:
//   f[b] = (((language[b] Wv + bv) Wv2 + bv2) Wo + bo) Wout + bout
//   out[b,t,:] = state[b,t,:] + f[b,:]
//
// Overlap: one cp.async.bulk per block streams the 96KB state tile on the TMA
// pipe during the whole GEMV chain; all 128 blocks cooperate on every stage
// (K-split partials, consumer-side deterministic reduction).
// ---------------------------------------------------------------------------
__global__ void __launch_bounds__(NTHR, 1)
fused_cma_kernel(const float* __restrict__ state,
                 const float* __restrict__ language,
                 const float* __restrict__ Wv,  const float* __restrict__ bv,
                 const float* __restrict__ Wv2, const float* __restrict__ bv2,
                 const float* __restrict__ Wo,  const float* __restrict__ bo,
                 const float* __restrict__ Wout,const float* __restrict__ bout,
                 float* __restrict__ out) {
    float4*   tile  = smem_dyn;                              // 6144 float4
    float*    sin   = (float*)(smem_dyn + TILE_F4);          // 192 floats
    float4*   spart = (float4*)(sin + 192);                  // 512 float4
    float4*   fsh   = spart + 512;                           // 96 float4
    uint64_t* mbar  = (uint64_t*)(fsh + 96);

    // ---- Issue state-tile bulk copy first (TMA pipe; overlaps the chain) ----
    const int bres = blockIdx.x >> 4;                        // batch
    const int t0   = (blockIdx.x & 15) * 64;                 // row start
    const size_t base = ((size_t)bres * TSEQ + t0) * DDIM;

    const uint32_t mbar_s = smem_u32(mbar);
    const uint32_t tile_s = smem_u32(tile);
    if (threadIdx.x == 0) {
        asm volatile("mbarrier.init.shared.b64 [%0], 1;" :: "r"(mbar_s) : "memory");
        asm volatile("fence.proxy.async.shared::cta;" ::: "memory");
        asm volatile("mbarrier.arrive.expect_tx.shared.b64 _, [%0], %1;"
                     :: "r"(mbar_s), "r"((unsigned)(TILE_F4 * 16)) : "memory");
        asm volatile(
            "cp.async.bulk.shared::cta.global.mbarrier::complete_tx::bytes "
            "[%0], [%1], %2, [%3];"
            :: "r"(tile_s), "l"(state + base), "r"((unsigned)(TILE_F4 * 16)),
               "r"(mbar_s) : "memory");
    }

    // ---- GEMV chain: 4 stages, all blocks, K-split partials ----
    chain_stage<DLANG, HID, 4, true >(language, Wv,   bv,   g_partA, sin, spart);
    grid_barrier(0);
    chain_stage<HID,   HID, 4, false>(g_partA,  Wv2,  bv2,  g_partB, sin, spart);
    grid_barrier(1);
    chain_stage<HID,   HID, 4, false>(g_partB,  Wo,   bo,   g_partA, sin, spart);
    grid_barrier(2);
    chain_stage<HID,  DDIM, 3, false>(g_partA,  Wout, bout, g_partB, sin, spart);
    grid_barrier(3);

    // ---- Assemble f row for this block's batch (deterministic sum) ----
    if (threadIdx.x < DDIM / 4) {
        const float4* p0 = (const float4*)(g_partB + (size_t)(0 * BATCH + bres) * DDIM);
        const float4* p1 = (const float4*)(g_partB + (size_t)(1 * BATCH + bres) * DDIM);
        const float4* p2 = (const float4*)(g_partB + (size_t)(2 * BATCH + bres) * DDIM);
        const float4* p3 = (const float4*)(g_partB + (size_t)(3 * BATCH + bres) * DDIM);
        float4 a = p0[threadIdx.x], b = p1[threadIdx.x];
        float4 c = p2[threadIdx.x], d = p3[threadIdx.x];
        a.x += b.x; a.y += b.y; a.z += b.z; a.w += b.w;
        c.x += d.x; c.y += d.y; c.z += d.z; c.w += d.w;
        a.x += c.x; a.y += c.y; a.z += c.z; a.w += c.w;
        fsh[threadIdx.x] = a;
    }
    __syncthreads();

    // Register-resident f values: p = tid + it*512; p mod 96 cycles through
    // {dq0, dq0+32, dq0+64} (512 mod 96 = 32, period 3).
    const int dq0 = threadIdx.x % (DDIM / 4);
    const int dq1 = (dq0 + 32) % (DDIM / 4);
    const int dq2 = (dq0 + 64) % (DDIM / 4);
    const float4 f0 = fsh[dq0], f1 = fsh[dq1], f2 = fsh[dq2];

    // ---- Wait for the state tile (mbarrier parity 0, acquire) ----
    {
        uint32_t done;
        asm volatile(
            "{\n\t.reg .pred p;\n\t"
            "mbarrier.try_wait.parity.acquire.cta.shared::cta.b64 p, [%1], 0;\n\t"
            "selp.b32 %0, 1, 0, p;\n\t}"
            : "=r"(done) : "r"(mbar_s) : "memory");
        if (!done) {
            asm volatile(
                "{\n\t.reg .pred P1;\n\t"
                "WL_%=:\n\t"
                "mbarrier.try_wait.parity.acquire.cta.shared::cta.b64 P1, [%0], 0, 0x989680;\n\t"
                "@P1 bra.uni WD_%=;\n\t"
                "bra.uni WL_%=;\n\t"
                "WD_%=:\n\t}"
                :: "r"(mbar_s) : "memory");
        }
    }

    // ---- Residual add + store: 6144 float4 per block, 12 per thread ----
    float4* op = (float4*)(out + base);
#pragma unroll
    for (int it = 0; it < 12; ++it) {
        const int p = threadIdx.x + it * NTHR;
        float4 s = tile[p];
        const float4 fv = (it % 3 == 0) ? f0 : ((it % 3 == 1) ? f1 : f2);
        s.x += fv.x; s.y += fv.y; s.z += fv.z; s.w += fv.w;
        op[p] = s;
    }
}

// ---------------------------------------------------------------------------
// Inputs (metadata order):
//  0 state [B,T,D]   1 language [B,DL]
//  2 Wq 3 bq 4 Wk 5 bk 6 Wv 7 bv
//  8 Wq2 9 bq2 10 Wk2 11 bk2 12 Wv2 13 bv2
// 14 Wo 15 bo 16 Wout 17 bout
// Output: float32 [B,T,D]
// ---------------------------------------------------------------------------
extern "C" void kernel_launch(void* const* d_in, const int* in_sizes, int n_in,
                              void* d_out, int out_size) {
    (void)in_sizes; (void)n_in; (void)out_size;

    const float* state    = (const float*)d_in[0];
    const float* language = (const float*)d_in[1];
    const float* Wv   = (const float*)d_in[6];
    const float* bv   = (const float*)d_in[7];
    const float* Wv2  = (const float*)d_in[12];
    const float* bv2  = (const float*)d_in[13];
    const float* Wo   = (const float*)d_in[14];
    const float* bo   = (const float*)d_in[15];
    const float* Wout = (const float*)d_in[16];
    const float* bout = (const float*)d_in[17];
    float* out = (float*)d_out;

    cudaFuncSetAttribute(fused_cma_kernel,
                         cudaFuncAttributeMaxDynamicSharedMemorySize,
                         SMEM_BYTES);

    // Single graph node: ticket barriers need no reset across replays.
    fused_cma_kernel<<<NB, NTHR, SMEM_BYTES>>>(state, language,
                                               Wv, bv, Wv2, bv2, Wo, bo,
                                               Wout, bout, out);
}

// round 10
// speedup vs baseline: 1.1339x; 1.0017x over previous
#include <cuda_runtime.h>
#include <cstdint>
#include <cstddef>

// Problem constants
#define BATCH 8
#define TSEQ  1024
#define DDIM  384
#define DLANG 768
#define HID   512

#define NB     128    // chain kernel: one wave, all blocks co-resident
#define NTHR_A 512
#define KSPLIT 4

// Scratch + barrier state (allocation-free rule: __device__ globals)
__device__ float g_partA[KSPLIT * BATCH * HID];
__device__ float g_partB[KSPLIT * BATCH * HID];
__device__ unsigned g_barrier[8];   // monotonic ticket counters; NEVER reset

// ---------------------------------------------------------------------------
// Monotonic ticket grid barrier (no reset across graph replays).
// ---------------------------------------------------------------------------
__device__ __forceinline__ void grid_barrier(int phase) {
    __syncthreads();
    if (threadIdx.x == 0) {
        __threadfence();
        const unsigned old = atomicAdd(&g_barrier[phase], 1u);
        const unsigned target = old - (old % NB) + NB;
        volatile unsigned* p = &g_barrier[phase];
        while ((int)(*p - target) < 0) { __nanosleep(16); }
        __threadfence();
    }
    __syncthreads();
}

// ---------------------------------------------------------------------------
// One K-split GEMV stage across all 128 blocks (direct LDG weights).
//   block -> (ks, idx): ks = blockIdx.x>>5, idx = blockIdx.x&31
//   active if idx < 8*JT;  b = idx/JT; jt = idx%JT (tile of 128 columns)
//   partial[ks][b][j] = sum_{i in ks-slice} in[b,i]*W[i,j]  (+bias if ks==0)
// FIRST: input dense [B][K]; else input = partials [KSPLIT][B][K] summed in
// fixed order (deterministic).
// ---------------------------------------------------------------------------
template <int K, int N, int JT, bool FIRST>
__device__ __forceinline__ void chain_stage(const float* __restrict__ in,
                                            const float* __restrict__ W,
                                            const float* __restrict__ bias,
                                            float* __restrict__ out_part,
                                            float* sin, float4* spart) {
    constexpr int K4 = K / KSPLIT;      // 192 or 128
    constexpr int KW = K4 / 16;         // 12 or 8
    const int ks  = blockIdx.x >> 5;
    const int idx = blockIdx.x & 31;
    const bool active = idx < 8 * JT;
    const int b  = idx / JT;
    const int jt = idx % JT;

    if (active && threadIdx.x < K4) {
        if (FIRST) {
            sin[threadIdx.x] = in[(size_t)b * K + ks * K4 + threadIdx.x];
        } else {
            const size_t o = (size_t)b * K + ks * K4 + threadIdx.x;
            float s = in[o];
            s += in[(size_t)(1 * BATCH) * K + o];
            s += in[(size_t)(2 * BATCH) * K + o];
            s += in[(size_t)(3 * BATCH) * K + o];
            sin[threadIdx.x] = s;
        }
    }
    __syncthreads();

    if (active) {
        const int w  = threadIdx.x >> 5;       // 0..15
        const int j4 = threadIdx.x & 31;
        constexpr int NC4 = N / 4;
        const float4* Wp = (const float4*)W
                         + (size_t)(ks * K4 + w * KW) * NC4 + jt * 32 + j4;
        const float* sp = sin + w * KW;
        float4 acc = {0.f, 0.f, 0.f, 0.f};
#pragma unroll
        for (int i = 0; i < KW; ++i) {
            const float s = sp[i];
            const float4 wv = Wp[(size_t)i * NC4];
            acc.x += s * wv.x; acc.y += s * wv.y;
            acc.z += s * wv.z; acc.w += s * wv.w;
        }
        spart[w * 32 + j4] = acc;
    }
    __syncthreads();

    if (active && threadIdx.x < 32) {
        float4 s = spart[threadIdx.x];
#pragma unroll
        for (int k = 1; k < 16; ++k) {
            const float4 v = spart[k * 32 + threadIdx.x];
            s.x += v.x; s.y += v.y; s.z += v.z; s.w += v.w;
        }
        if (ks == 0) {
            const float4 bb = ((const float4*)bias)[jt * 32 + threadIdx.x];
            s.x += bb.x; s.y += bb.y; s.z += bb.z; s.w += bb.w;
        }
        ((float4*)(out_part + (size_t)(ks * BATCH + b) * N))
            [jt * 32 + threadIdx.x] = s;
    }
    // sin/spart reuse by the next stage is protected by grid_barrier's syncs.
}

// ---------------------------------------------------------------------------
// Kernel A: the GEMV chain. Triggers PDL at entry so the residual kernel can
// co-schedule and stream `state` while this runs. Final stage leaves f as 4
// K-split partials in g_partB; kernel B assembles them (kernel boundary is
// the producer-consumer sync, so no 4th barrier).
//
// Math note: language is broadcast along T, so k/v are identical for all key
// positions; softmax over a constant row is exactly uniform 1/T and ctx == v.
// The Q path and the T x T attention cancel analytically:
//   f[b] = (((language[b] Wv + bv) Wv2 + bv2) Wo + bo) Wout + bout
//   out[b,t,:] = state[b,t,:] + f[b,:]
// ---------------------------------------------------------------------------
__global__ void __launch_bounds__(NTHR_A, 1)
chain_kernel(const float* __restrict__ language,
             const float* __restrict__ Wv,  const float* __restrict__ bv,
             const float* __restrict__ Wv2, const float* __restrict__ bv2,
             const float* __restrict__ Wo,  const float* __restrict__ bo,
             const float* __restrict__ Wout,const float* __restrict__ bout) {
    if (threadIdx.x == 0) cudaTriggerProgrammaticLaunchCompletion();

    __shared__ float  sin[192];
    __shared__ float4 spart[512];

    chain_stage<DLANG, HID, 4, true >(language, Wv,   bv,   g_partA, sin, spart);
    grid_barrier(0);
    chain_stage<HID,   HID, 4, false>(g_partA,  Wv2,  bv2,  g_partB, sin, spart);
    grid_barrier(1);
    chain_stage<HID,   HID, 4, false>(g_partB,  Wo,   bo,   g_partA, sin, spart);
    grid_barrier(2);
    chain_stage<HID,  DDIM, 3, false>(g_partA,  Wout, bout, g_partB, sin, spart);
}

// ---------------------------------------------------------------------------
// Kernel B: residual broadcast add. Launched with programmatic stream
// serialization: co-schedules with kernel A, loads its state tile into
// registers DURING the chain, then grid-dep-syncs, assembles f, adds, stores.
// Grid (64, 8): 512 blocks x 256 thr, 16 rows of 384 floats per block.
// ---------------------------------------------------------------------------
__global__ void __launch_bounds__(256)
residual_kernel(const float* __restrict__ state, float* __restrict__ out) {
    const int b  = blockIdx.y;
    const int t0 = blockIdx.x * 16;
    const size_t base = ((size_t)b * TSEQ + t0) * DDIM;
    const float4* sp = (const float4*)(state + base);

    // 16 rows * 96 float4 = 1536 float4 -> 6 per thread, loaded pre-sync.
    float4 s0 = sp[threadIdx.x +  0 * 256];
    float4 s1 = sp[threadIdx.x +  1 * 256];
    float4 s2 = sp[threadIdx.x +  2 * 256];
    float4 s3 = sp[threadIdx.x +  3 * 256];
    float4 s4 = sp[threadIdx.x +  4 * 256];
    float4 s5 = sp[threadIdx.x +  5 * 256];

    // Wait for the chain kernel's partials to be visible.
    cudaGridDependencySynchronize();

    __shared__ float4 fsh[DDIM / 4];   // 96
    if (threadIdx.x < DDIM / 4) {
        const float4* p0 = (const float4*)(g_partB + (size_t)(0 * BATCH + b) * DDIM);
        const float4* p1 = (const float4*)(g_partB + (size_t)(1 * BATCH + b) * DDIM);
        const float4* p2 = (const float4*)(g_partB + (size_t)(2 * BATCH + b) * DDIM);
        const float4* p3 = (const float4*)(g_partB + (size_t)(3 * BATCH + b) * DDIM);
        float4 a = p0[threadIdx.x], bb = p1[threadIdx.x];
        float4 c = p2[threadIdx.x], d  = p3[threadIdx.x];
        a.x += bb.x; a.y += bb.y; a.z += bb.z; a.w += bb.w;
        c.x += d.x;  c.y += d.y;  c.z += d.z;  c.w += d.w;
        a.x += c.x;  a.y += c.y;  a.z += c.z;  a.w += c.w;
        fsh[threadIdx.x] = a;
    }
    __syncthreads();

    // p = tid + it*256; p mod 96 cycles {dq0, dq0+64, dq0+32} (256 mod 96 = 64).
    const int dq0 = threadIdx.x % (DDIM / 4);
    const float4 f0 = fsh[dq0];
    const float4 f1 = fsh[(dq0 + 64) % (DDIM / 4)];
    const float4 f2 = fsh[(dq0 + 32) % (DDIM / 4)];

    float4* op = (float4*)(out + base);
    s0.x += f0.x; s0.y += f0.y; s0.z += f0.z; s0.w += f0.w; op[threadIdx.x + 0*256] = s0;
    s1.x += f1.x; s1.y += f1.y; s1.z += f1.z; s1.w += f1.w; op[threadIdx.x + 1*256] = s1;
    s2.x += f2.x; s2.y += f2.y; s2.z += f2.z; s2.w += f2.w; op[threadIdx.x + 2*256] = s2;
    s3.x += f0.x; s3.y += f0.y; s3.z += f0.z; s3.w += f0.w; op[threadIdx.x + 3*256] = s3;
    s4.x += f1.x; s4.y += f1.y; s4.z += f1.z; s4.w += f1.w; op[threadIdx.x + 4*256] = s4;
    s5.x += f2.x; s5.y += f2.y; s5.z += f2.z; s5.w += f2.w; op[threadIdx.x + 5*256] = s5;
}

// ---------------------------------------------------------------------------
// Inputs (metadata order):
//  0 state [B,T,D]   1 language [B,DL]
//  2 Wq 3 bq 4 Wk 5 bk 6 Wv 7 bv
//  8 Wq2 9 bq2 10 Wk2 11 bk2 12 Wv2 13 bv2
// 14 Wo 15 bo 16 Wout 17 bout
// Output: float32 [B,T,D]
// ---------------------------------------------------------------------------
extern "C" void kernel_launch(void* const* d_in, const int* in_sizes, int n_in,
                              void* d_out, int out_size) {
    (void)in_sizes; (void)n_in; (void)out_size;

    const float* state    = (const float*)d_in[0];
    const float* language = (const float*)d_in[1];
    const float* Wv   = (const float*)d_in[6];
    const float* bv   = (const float*)d_in[7];
    const float* Wv2  = (const float*)d_in[12];
    const float* bv2  = (const float*)d_in[13];
    const float* Wo   = (const float*)d_in[14];
    const float* bo   = (const float*)d_in[15];
    const float* Wout = (const float*)d_in[16];
    const float* bout = (const float*)d_in[17];
    float* out = (float*)d_out;

    // Kernel A: GEMV chain (ticket barriers -> no reset node needed).
    chain_kernel<<<NB, NTHR_A>>>(language, Wv, bv, Wv2, bv2, Wo, bo,
                                 Wout, bout);

    // Kernel B: residual add, PDL so it co-schedules with A and streams
    // `state` while the chain runs.
    cudaLaunchConfig_t cfg = {};
    cfg.gridDim  = dim3(TSEQ / 16, BATCH, 1);
    cfg.blockDim = dim3(256, 1, 1);
    cfg.dynamicSmemBytes = 0;
    cfg.stream = 0;
    cudaLaunchAttribute attrs[1];
    attrs[0].id = cudaLaunchAttributeProgrammaticStreamSerialization;
    attrs[0].val.programmaticStreamSerializationAllowed = 1;
    cfg.attrs = attrs;
    cfg.numAttrs = 1;
    cudaLaunchKernelEx(&cfg, residual_kernel, state, out);
}